// round 13
// baseline (speedup 1.0000x reference)
#include <cuda_runtime.h>
#include <cuda_fp16.h>

// TriplesDistances: B=16, N=512, A=1024
// positions [B,N,3] f32; neighbors_j/k [B,N,A] int32; out = concat(r_ij,r_ik,r_jk) f32
//
// R12: L1=66% / occ=64% / nothing saturated -> un-hidden gather latency; the
// fix is MORE WARPS, not more ILP. R11: 512-thread blocks, warps 0-7 -> row
// bn0, warps 8-15 -> row bn0+1; one row per thread shrinks live state so
// launch_bounds(512,4) forces regs<=32 -> 64 warps/SM (100% theoretical).
// Grid stays 4096; per-element wavefronts unchanged.
//  - half-packed {half2 xy, half z} table, ONE LDS.64 per gather
//  - pi from same table -> exact 0 at j==n / j==k
//  - sqrt.approx.f32, no s>0 guard

#define BB 16
#define NN 512
#define AA 1024
#define THREADS 512
#define CH 2

__device__ __forceinline__ float sqrt_approx(float s) {
    float r;
    asm("sqrt.approx.f32 %0, %1;" : "=f"(r) : "f"(s));
    return r;
}

struct PosF { float x, y, z; };

__device__ __forceinline__ PosF unpack_pos(uint2 v) {
    __half2 xy = *reinterpret_cast<__half2*>(&v.x);
    float2  f  = __half22float2(xy);
    PosF p;
    p.x = f.x;
    p.y = f.y;
    p.z = __half2float(__ushort_as_half((unsigned short)v.y));
    return p;
}

__global__ void __launch_bounds__(THREADS, 4)
triples_distances_kernel(const float* __restrict__ positions,
                         const int* __restrict__ nj,
                         const int* __restrict__ nk,
                         float* __restrict__ out)
{
    __shared__ uint2 sp[NN];   // 4 KB: {half2 xy, half z}

    const int bn0 = blockIdx.x * CH;          // first (b,n) row of this block
    const int b   = bn0 >> 9;                 // / 512
    const int n0  = bn0 & (NN - 1);

    const int row = threadIdx.x >> 8;         // 0 or 1: which of the 2 rows
    const int lane256 = threadIdx.x & 255;    // position within the row's 256 threads
    const unsigned a0 = lane256 * 4;          // 4 elements/thread covers A=1024
    const unsigned e  = ((unsigned)bn0 + row) * AA + a0;

    // One index quad per array per thread, hoisted above staging.
    const int4 j4 = *reinterpret_cast<const int4*>(nj + e);
    const int4 k4 = *reinterpret_cast<const int4*>(nk + e);

    // Stage positions[b] as packed half {x,y,z}: 1 atom per thread.
    {
        const float* pbase = positions + b * (NN * 3);
        const int i = threadIdx.x;            // THREADS == NN
        const float x = pbase[3*i + 0];
        const float y = pbase[3*i + 1];
        const float z = pbase[3*i + 2];
        __half2 xy = __floats2half2_rn(x, y);
        uint2 v;
        v.x = *reinterpret_cast<const unsigned*>(&xy);
        v.y = (unsigned)__half_as_ushort(__float2half_rn(z));
        sp[i] = v;
    }
    __syncthreads();

    const unsigned T = (unsigned)BB * NN * AA;

    const PosF pi = unpack_pos(sp[n0 + row]); // broadcast within each half-block

    const int ji[4] = { j4.x, j4.y, j4.z, j4.w };
    const int ki[4] = { k4.x, k4.y, k4.z, k4.w };

    float rij[4], rik[4], rjk[4];
    #pragma unroll
    for (int t = 0; t < 4; t++) {
        const PosF pj = unpack_pos(sp[ji[t]]);
        const PosF pk = unpack_pos(sp[ki[t]]);

        float dx = pj.x - pi.x, dy = pj.y - pi.y, dz = pj.z - pi.z;
        rij[t] = sqrt_approx(dx*dx + dy*dy + dz*dz);

        dx = pk.x - pi.x; dy = pk.y - pi.y; dz = pk.z - pi.z;
        rik[t] = sqrt_approx(dx*dx + dy*dy + dz*dz);

        dx = pj.x - pk.x; dy = pj.y - pk.y; dz = pj.z - pk.z;
        rjk[t] = sqrt_approx(dx*dx + dy*dy + dz*dz);
    }

    *reinterpret_cast<float4*>(out + e)         = make_float4(rij[0], rij[1], rij[2], rij[3]);
    *reinterpret_cast<float4*>(out + T + e)     = make_float4(rik[0], rik[1], rik[2], rik[3]);
    *reinterpret_cast<float4*>(out + 2u*T + e)  = make_float4(rjk[0], rjk[1], rjk[2], rjk[3]);
}

extern "C" void kernel_launch(void* const* d_in, const int* in_sizes, int n_in,
                              void* d_out, int out_size)
{
    const float* positions = (const float*)d_in[0];
    const int*   nj        = (const int*)d_in[1];
    const int*   nk        = (const int*)d_in[2];
    float*       out       = (float*)d_out;

    dim3 grid(BB * NN / CH);   // 4096 blocks
    dim3 block(THREADS);
    triples_distances_kernel<<<grid, block>>>(positions, nj, nk, out);
}

// round 14
// speedup vs baseline: 1.0645x; 1.0645x over previous
#include <cuda_runtime.h>
#include <cuda_fp16.h>

// TriplesDistances: B=16, N=512, A=1024
// positions [B,N,3] f32; neighbors_j/k [B,N,A] int32; out = concat(r_ij,r_ik,r_jk) f32
//
// Law from R4..R13: time x L1% ~= const (fixed crossbar wavefront work); only
// feed-efficiency moves time. R13 (512 thr, regs=28) broke code quality.
// R14 = R12 proven shape (grid 4096, CH=2, 256 thr) with the gentlest
// occupancy lever: launch_bounds(256,7) -> regs<=36, 56 warps/SM.
//  - half-packed {half2 xy, half z} table, ONE LDS.64 per gather
//  - pi from same table -> exact 0 at j==n / j==k
//  - sqrt.approx.f32, no s>0 guard

#define BB 16
#define NN 512
#define AA 1024
#define THREADS 256
#define CH 2

__device__ __forceinline__ float sqrt_approx(float s) {
    float r;
    asm("sqrt.approx.f32 %0, %1;" : "=f"(r) : "f"(s));
    return r;
}

struct PosF { float x, y, z; };

__device__ __forceinline__ PosF unpack_pos(uint2 v) {
    __half2 xy = *reinterpret_cast<__half2*>(&v.x);
    float2  f  = __half22float2(xy);
    PosF p;
    p.x = f.x;
    p.y = f.y;
    p.z = __half2float(__ushort_as_half((unsigned short)v.y));
    return p;
}

__global__ void __launch_bounds__(THREADS, 7)
triples_distances_kernel(const float* __restrict__ positions,
                         const int* __restrict__ nj,
                         const int* __restrict__ nk,
                         float* __restrict__ out)
{
    __shared__ uint2 sp[NN];   // 4 KB: {half2 xy, half z}

    const int bn0 = blockIdx.x * CH;        // first (b,n) row of this block
    const int b   = bn0 >> 9;               // / 512
    const int n0  = bn0 & (NN - 1);

    const unsigned a0    = threadIdx.x * 4; // 4 elements/thread covers A=1024
    const unsigned base0 = (unsigned)bn0 * AA + a0;

    // Hoist all index loads (4 independent LDG.128) above the staging.
    const int4 j4_0 = *reinterpret_cast<const int4*>(nj + base0);
    const int4 k4_0 = *reinterpret_cast<const int4*>(nk + base0);
    const int4 j4_1 = *reinterpret_cast<const int4*>(nj + base0 + AA);
    const int4 k4_1 = *reinterpret_cast<const int4*>(nk + base0 + AA);

    // Stage positions[b] as packed half {x,y,z} (8 B/atom).
    {
        const float* pbase = positions + b * (NN * 3);
        #pragma unroll
        for (int i = threadIdx.x; i < NN; i += THREADS) {
            const float x = pbase[3*i + 0];
            const float y = pbase[3*i + 1];
            const float z = pbase[3*i + 2];
            __half2 xy = __floats2half2_rn(x, y);
            uint2 v;
            v.x = *reinterpret_cast<const unsigned*>(&xy);
            v.y = (unsigned)__half_as_ushort(__float2half_rn(z));
            sp[i] = v;
        }
    }
    __syncthreads();

    const unsigned T = (unsigned)BB * NN * AA;

    const PosF pi0 = unpack_pos(sp[n0]);
    const PosF pi1 = unpack_pos(sp[n0 + 1]);

    #pragma unroll
    for (int nn = 0; nn < CH; nn++) {
        const int4 j4 = (nn == 0) ? j4_0 : j4_1;
        const int4 k4 = (nn == 0) ? k4_0 : k4_1;
        const PosF pi = (nn == 0) ? pi0  : pi1;
        const unsigned e = base0 + (unsigned)nn * AA;

        const int ji[4] = { j4.x, j4.y, j4.z, j4.w };
        const int ki[4] = { k4.x, k4.y, k4.z, k4.w };

        // Issue all 8 gathers of this row before any consumption.
        uint2 gj[4], gk[4];
        #pragma unroll
        for (int t = 0; t < 4; t++) gj[t] = sp[ji[t]];
        #pragma unroll
        for (int t = 0; t < 4; t++) gk[t] = sp[ki[t]];

        float rij[4], rik[4], rjk[4];
        #pragma unroll
        for (int t = 0; t < 4; t++) {
            const PosF pj = unpack_pos(gj[t]);
            const PosF pk = unpack_pos(gk[t]);

            float dx = pj.x - pi.x, dy = pj.y - pi.y, dz = pj.z - pi.z;
            rij[t] = sqrt_approx(dx*dx + dy*dy + dz*dz);

            dx = pk.x - pi.x; dy = pk.y - pi.y; dz = pk.z - pi.z;
            rik[t] = sqrt_approx(dx*dx + dy*dy + dz*dz);

            dx = pj.x - pk.x; dy = pj.y - pk.y; dz = pj.z - pk.z;
            rjk[t] = sqrt_approx(dx*dx + dy*dy + dz*dz);
        }

        *reinterpret_cast<float4*>(out + e)         = make_float4(rij[0], rij[1], rij[2], rij[3]);
        *reinterpret_cast<float4*>(out + T + e)     = make_float4(rik[0], rik[1], rik[2], rik[3]);
        *reinterpret_cast<float4*>(out + 2u*T + e)  = make_float4(rjk[0], rjk[1], rjk[2], rjk[3]);
    }
}

extern "C" void kernel_launch(void* const* d_in, const int* in_sizes, int n_in,
                              void* d_out, int out_size)
{
    const float* positions = (const float*)d_in[0];
    const int*   nj        = (const int*)d_in[1];
    const int*   nk        = (const int*)d_in[2];
    float*       out       = (float*)d_out;

    dim3 grid(BB * NN / CH);   // 4096 blocks
    dim3 block(THREADS);
    triples_distances_kernel<<<grid, block>>>(positions, nj, nk, out);
}

// round 16
// speedup vs baseline: 1.0656x; 1.0010x over previous
#include <cuda_runtime.h>
#include <cuda_fp16.h>

// TriplesDistances: B=16, N=512, A=1024
// positions [B,N,3] f32; neighbors_j/k [B,N,A] int32; out = concat(r_ij,r_ik,r_jk) f32
//
// Ledger: 67 MB read-once (indices) + 101 MB write-once (out) = 168 MB.
// R12 kernel = 25.6 us -> 6.55 TB/s ~ 82% of spec: at the memory roof.
// R15 = R12 proven shape + streaming cache hints (__ldcs index loads,
// __stcs output stores) so the read/write-once streams evict-first in L2,
// leaving L2 to the position tables (read 256x each).
//  - half-packed {half2 xy, half z} table, ONE LDS.64 per gather
//  - pi from same table -> exact 0 at j==n / j==k
//  - sqrt.approx.f32, no s>0 guard, launch_bounds(256,6), grid 4096, CH=2

#define BB 16
#define NN 512
#define AA 1024
#define THREADS 256
#define CH 2

__device__ __forceinline__ float sqrt_approx(float s) {
    float r;
    asm("sqrt.approx.f32 %0, %1;" : "=f"(r) : "f"(s));
    return r;
}

struct PosF { float x, y, z; };

__device__ __forceinline__ PosF unpack_pos(uint2 v) {
    __half2 xy = *reinterpret_cast<__half2*>(&v.x);
    float2  f  = __half22float2(xy);
    PosF p;
    p.x = f.x;
    p.y = f.y;
    p.z = __half2float(__ushort_as_half((unsigned short)v.y));
    return p;
}

__global__ void __launch_bounds__(THREADS, 6)
triples_distances_kernel(const float* __restrict__ positions,
                         const int* __restrict__ nj,
                         const int* __restrict__ nk,
                         float* __restrict__ out)
{
    __shared__ uint2 sp[NN];   // 4 KB: {half2 xy, half z}

    const int bn0 = blockIdx.x * CH;        // first (b,n) row of this block
    const int b   = bn0 >> 9;               // / 512
    const int n0  = bn0 & (NN - 1);

    const unsigned a0    = threadIdx.x * 4; // 4 elements/thread covers A=1024
    const unsigned base0 = (unsigned)bn0 * AA + a0;

    // Hoist all index loads (4 independent LDG.128, evict-first) above staging.
    const int4 j4_0 = __ldcs(reinterpret_cast<const int4*>(nj + base0));
    const int4 k4_0 = __ldcs(reinterpret_cast<const int4*>(nk + base0));
    const int4 j4_1 = __ldcs(reinterpret_cast<const int4*>(nj + base0 + AA));
    const int4 k4_1 = __ldcs(reinterpret_cast<const int4*>(nk + base0 + AA));

    // Stage positions[b] as packed half {x,y,z} (8 B/atom).
    {
        const float* pbase = positions + b * (NN * 3);
        #pragma unroll
        for (int i = threadIdx.x; i < NN; i += THREADS) {
            const float x = pbase[3*i + 0];
            const float y = pbase[3*i + 1];
            const float z = pbase[3*i + 2];
            __half2 xy = __floats2half2_rn(x, y);
            uint2 v;
            v.x = *reinterpret_cast<const unsigned*>(&xy);
            v.y = (unsigned)__half_as_ushort(__float2half_rn(z));
            sp[i] = v;
        }
    }
    __syncthreads();

    const unsigned T = (unsigned)BB * NN * AA;

    const PosF pi0 = unpack_pos(sp[n0]);
    const PosF pi1 = unpack_pos(sp[n0 + 1]);

    #pragma unroll
    for (int nn = 0; nn < CH; nn++) {
        const int4 j4 = (nn == 0) ? j4_0 : j4_1;
        const int4 k4 = (nn == 0) ? k4_0 : k4_1;
        const PosF pi = (nn == 0) ? pi0  : pi1;
        const unsigned e = base0 + (unsigned)nn * AA;

        const int ji[4] = { j4.x, j4.y, j4.z, j4.w };
        const int ki[4] = { k4.x, k4.y, k4.z, k4.w };

        // Issue all 8 gathers of this row before any consumption.
        uint2 gj[4], gk[4];
        #pragma unroll
        for (int t = 0; t < 4; t++) gj[t] = sp[ji[t]];
        #pragma unroll
        for (int t = 0; t < 4; t++) gk[t] = sp[ki[t]];

        float rij[4], rik[4], rjk[4];
        #pragma unroll
        for (int t = 0; t < 4; t++) {
            const PosF pj = unpack_pos(gj[t]);
            const PosF pk = unpack_pos(gk[t]);

            float dx = pj.x - pi.x, dy = pj.y - pi.y, dz = pj.z - pi.z;
            rij[t] = sqrt_approx(dx*dx + dy*dy + dz*dz);

            dx = pk.x - pi.x; dy = pk.y - pi.y; dz = pk.z - pi.z;
            rik[t] = sqrt_approx(dx*dx + dy*dy + dz*dz);

            dx = pj.x - pk.x; dy = pj.y - pk.y; dz = pj.z - pk.z;
            rjk[t] = sqrt_approx(dx*dx + dy*dy + dz*dz);
        }

        // Streaming stores: write-once data, evict-first in L2.
        __stcs(reinterpret_cast<float4*>(out + e),
               make_float4(rij[0], rij[1], rij[2], rij[3]));
        __stcs(reinterpret_cast<float4*>(out + T + e),
               make_float4(rik[0], rik[1], rik[2], rik[3]));
        __stcs(reinterpret_cast<float4*>(out + 2u*T + e),
               make_float4(rjk[0], rjk[1], rjk[2], rjk[3]));
    }
}

extern "C" void kernel_launch(void* const* d_in, const int* in_sizes, int n_in,
                              void* d_out, int out_size)
{
    const float* positions = (const float*)d_in[0];
    const int*   nj        = (const int*)d_in[1];
    const int*   nk        = (const int*)d_in[2];
    float*       out       = (float*)d_out;

    dim3 grid(BB * NN / CH);   // 4096 blocks
    dim3 block(THREADS);
    triples_distances_kernel<<<grid, block>>>(positions, nj, nk, out);
}